// round 13
// baseline (speedup 1.0000x reference)
#include <cuda_runtime.h>
#include <cuda_fp16.h>
#include <cstdint>

// Problem dims
#define S_LEN 1024
#define BATCH 64
#define IDIM  512
#define HDIM  2048
#define ODIM  512
#define MTOT  (S_LEN * BATCH)   // 65536

// ---------------------------------------------------------------------------
// Device scratch (no cudaMalloc allowed)
// ---------------------------------------------------------------------------
__device__ __half g_Xh[(size_t)MTOT * IDIM];        // 64 MB   fp16 X
__device__ __half g_Wh[(size_t)HDIM * IDIM];        // 2 MB    fp16 W_ih
__device__ __half g_uh[(size_t)MTOT * HDIM];        // 256 MB  u (fp16)
__device__ float  g_h [(size_t)BATCH * HDIM];       // 512 KB  h_final[b][h]
__device__ float  g_part[(size_t)32 * BATCH * ODIM];// 4 MB    split-K partials

// ---------------------------------------------------------------------------
// Helpers
// ---------------------------------------------------------------------------
__device__ __forceinline__ void cp_async16(uint32_t saddr, const void* gptr) {
    asm volatile("cp.async.cg.shared.global [%0], [%1], 16;\n"
                 :: "r"(saddr), "l"(gptr) : "memory");
}
#define CP_COMMIT() asm volatile("cp.async.commit_group;\n" ::: "memory")
#define CP_WAIT(N)  asm volatile("cp.async.wait_group %0;\n" :: "n"(N) : "memory")

#define LDSM_X4(r0, r1, r2, r3, addr) \
    asm volatile("ldmatrix.sync.aligned.m8n8.x4.shared.b16 {%0,%1,%2,%3}, [%4];" \
                 : "=r"(r0), "=r"(r1), "=r"(r2), "=r"(r3) : "r"(addr))

struct alignas(16) H8 { __half2 a, b, c, d; };

// ---------------------------------------------------------------------------
// Kernel 1: fused fp32 -> fp16 conversion prepass (X then W in one grid)
// ---------------------------------------------------------------------------
#define NX_H8 (MTOT * IDIM / 8)          // 4,194,304
#define NW_H8 (HDIM * IDIM / 8)          // 131,072

__global__ void cvt_kernel(const float4* __restrict__ X,
                           const float4* __restrict__ W) {
    int i = blockIdx.x * blockDim.x + threadIdx.x;
    const float4* src;
    H8* dst;
    int j;
    if (i < NX_H8) {
        src = X;  dst = reinterpret_cast<H8*>(g_Xh);  j = i;
    } else {
        src = W;  dst = reinterpret_cast<H8*>(g_Wh);  j = i - NX_H8;
    }
    float4 v0 = src[2 * j], v1 = src[2 * j + 1];
    H8 o;
    o.a = __floats2half2_rn(v0.x, v0.y);
    o.b = __floats2half2_rn(v0.z, v0.w);
    o.c = __floats2half2_rn(v1.x, v1.y);
    o.d = __floats2half2_rn(v1.z, v1.w);
    dst[j] = o;
}

// ---------------------------------------------------------------------------
// Kernel 2: u = Xh @ Wh^T via mma.sync.m16n8k16 + ldmatrix.
// EXACT R10 configuration (best measured: 357 TF/s) with ONE change:
// the trailing __syncthreads is removed.  Safety: iteration kt's prefetch
// writes stage (kt-1)%3; all other warps' reads of that stage occurred in
// their iteration kt-1 compute, program-ordered before they arrived at
// iteration kt's top barrier, and the prefetch issues after that barrier.
// reads < barrier < writes holds for every warp pair.
// ---------------------------------------------------------------------------
#define BM 128
#define BN 128
#define BKH 32
#define KTILES (IDIM / BKH)        // 16
#define NSTG 3
#define LDAH 40
#define STAGE_HALFS (BM * LDAH)
#define STAGE_BYTES (STAGE_HALFS * 2)

__global__ __launch_bounds__(256, 2) void gemm_u_kernel() {
    __shared__ __half sA[NSTG][STAGE_HALFS];
    __shared__ __half sB[NSTG][STAGE_HALFS];

    const int tid  = threadIdx.x;
    const int lane = tid & 31;
    const int warp = tid >> 5;
    const int wm   = warp >> 1;   // 0..3
    const int wn   = warp & 1;    // 0..1
    const int g    = lane >> 2;   // 0..7
    const int tg   = lane & 3;    // 0..3

    const int m0 = blockIdx.y * BM;
    const int n0 = blockIdx.x * BN;

    const uint32_t sA_base = (uint32_t)__cvta_generic_to_shared(&sA[0][0]);
    const uint32_t sB_base = (uint32_t)__cvta_generic_to_shared(&sB[0][0]);

    // Per-lane ldmatrix byte offsets (validated R10 mapping).
    const int ro  = lane & 7;
    const int sel = lane >> 3;
    uint32_t offA[2], offB[4];
#pragma unroll
    for (int mi = 0; mi < 2; mi++) {
        int rowA = wm * 32 + mi * 16 + (sel & 1) * 8 + ro;
        int colA = (sel >> 1) * 8;
        offA[mi] = (uint32_t)(rowA * LDAH + colA) * 2;
    }
#pragma unroll
    for (int p = 0; p < 4; p++) {
        int rowB = wn * 64 + p * 16 + (sel >> 1) * 8 + ro;
        int colB = (sel & 1) * 8;
        offB[p] = (uint32_t)(rowB * LDAH + colB) * 2;
    }

    float c[2][8][4];
#pragma unroll
    for (int mi = 0; mi < 2; mi++)
#pragma unroll
        for (int ni = 0; ni < 8; ni++)
#pragma unroll
            for (int r = 0; r < 4; r++) c[mi][ni][r] = 0.0f;

    auto loadAB = [&](int stage, int kt) {
#pragma unroll
        for (int i = 0; i < 2; i++) {
            int lin = tid + i * 256;
            int row = lin >> 2, c16 = lin & 3;
            cp_async16(sA_base + stage * STAGE_BYTES + (row * LDAH + c16 * 8) * 2,
                       g_Xh + (size_t)(m0 + row) * IDIM + kt * BKH + c16 * 8);
            cp_async16(sB_base + stage * STAGE_BYTES + (row * LDAH + c16 * 8) * 2,
                       g_Wh + (size_t)(n0 + row) * IDIM + kt * BKH + c16 * 8);
        }
    };

    loadAB(0, 0); CP_COMMIT();
    loadAB(1, 1); CP_COMMIT();

    for (int kt = 0; kt < KTILES; ++kt) {
        if (kt < KTILES - 1) { CP_WAIT(1); } else { CP_WAIT(0); }
        __syncthreads();

        if (kt + 2 < KTILES) { loadAB((kt + 2) % NSTG, kt + 2); CP_COMMIT(); }

        const uint32_t aStage = sA_base + (kt % NSTG) * STAGE_BYTES;
        const uint32_t bStage = sB_base + (kt % NSTG) * STAGE_BYTES;
#pragma unroll
        for (int kf = 0; kf < 2; ++kf) {
            const uint32_t kbyte = kf * 32;   // 16 halves
            uint32_t a[2][4], bf[8][2];
#pragma unroll
            for (int mi = 0; mi < 2; mi++)
                LDSM_X4(a[mi][0], a[mi][1], a[mi][2], a[mi][3],
                        aStage + offA[mi] + kbyte);
#pragma unroll
            for (int p = 0; p < 4; p++)
                LDSM_X4(bf[2 * p][0], bf[2 * p][1], bf[2 * p + 1][0],
                        bf[2 * p + 1][1], bStage + offB[p] + kbyte);
#pragma unroll
            for (int mi = 0; mi < 2; mi++)
#pragma unroll
                for (int ni = 0; ni < 8; ni++) {
                    asm volatile(
                        "mma.sync.aligned.m16n8k16.row.col.f32.f16.f16.f32 "
                        "{%0,%1,%2,%3}, {%4,%5,%6,%7}, {%8,%9}, {%0,%1,%2,%3};"
                        : "+f"(c[mi][ni][0]), "+f"(c[mi][ni][1]),
                          "+f"(c[mi][ni][2]), "+f"(c[mi][ni][3])
                        : "r"(a[mi][0]), "r"(a[mi][1]), "r"(a[mi][2]), "r"(a[mi][3]),
                          "r"(bf[ni][0]), "r"(bf[ni][1]));
                }
        }
        // trailing __syncthreads removed (see header comment for proof)
    }

#pragma unroll
    for (int mi = 0; mi < 2; mi++) {
#pragma unroll
        for (int ni = 0; ni < 8; ni++) {
            int r     = m0 + wm * 32 + mi * 16 + g;
            int cbase = n0 + wn * 64 + ni * 8 + 2 * tg;
            __half2 v0 = __floats2half2_rn(c[mi][ni][0], c[mi][ni][1]);
            __half2 v1 = __floats2half2_rn(c[mi][ni][2], c[mi][ni][3]);
            *reinterpret_cast<__half2*>(g_uh + (size_t)r * HDIM + cbase)       = v0;
            *reinterpret_cast<__half2*>(g_uh + (size_t)(r + 8) * HDIM + cbase) = v1;
        }
    }
}

// ---------------------------------------------------------------------------
// Kernel 3: sequential scan h = |u_t + hh*h|, fp16 u, 2 channels/thread.
// 1024 CTAs x 64 thr, depth-32 prefetch ring (8 MB in flight).
// ---------------------------------------------------------------------------
#define SCAN_DEPTH 32

__global__ void scan_kernel(const float* __restrict__ hh) {
    const int ch2 = blockIdx.x * blockDim.x + threadIdx.x;   // half2 index
    const int hpair = (2 * ch2) & (HDIM - 1);
    const float a0 = hh[hpair];
    const float a1 = hh[hpair + 1];
    const __half2* p = reinterpret_cast<const __half2*>(g_uh) + ch2;
    const size_t stride = (size_t)BATCH * HDIM / 2;          // 65536 half2s

    __half2 buf[SCAN_DEPTH];
#pragma unroll
    for (int i = 0; i < SCAN_DEPTH; i++) buf[i] = p[(size_t)i * stride];

    float h0 = 0.0f, h1 = 0.0f;
    for (int s0 = 0; s0 < S_LEN; s0 += SCAN_DEPTH) {
#pragma unroll
        for (int i = 0; i < SCAN_DEPTH; i++) {
            float2 u = __half22float2(buf[i]);
            int ns = s0 + SCAN_DEPTH + i;
            if (ns < S_LEN) buf[i] = p[(size_t)ns * stride];
            h0 = fabsf(fmaf(a0, h0, u.x));
            h1 = fabsf(fmaf(a1, h1, u.y));
        }
    }
    *reinterpret_cast<float2*>(g_h + 2 * ch2) = make_float2(h0, h1);
}

// ---------------------------------------------------------------------------
// Kernel 4/5: split-K output GEMM (KSLICES=32) + reduce
// ---------------------------------------------------------------------------
#define KSLICES 32

__global__ __launch_bounds__(256) void out_partial_kernel(const float* __restrict__ W_ho) {
    __shared__ float sh[64][65];
    __shared__ float sw[64][65];
    const int tid = threadIdx.x;
    const int tx = tid & 15, ty = tid >> 4;
    const int o0 = blockIdx.x * 64;
    const int ks = blockIdx.y;
    const int kbase = ks * 64;

    float acc[4][4];
#pragma unroll
    for (int i = 0; i < 4; i++)
#pragma unroll
        for (int j = 0; j < 4; j++) acc[i][j] = 0.0f;

#pragma unroll
    for (int i = 0; i < 16; i++) {
        int lin = tid + i * 256;
        int row = lin >> 6, col = lin & 63;
        sh[row][col] = g_h[(size_t)row * HDIM + kbase + col];
        sw[row][col] = W_ho[(size_t)(o0 + row) * HDIM + kbase + col];
    }
    __syncthreads();
#pragma unroll 8
    for (int k = 0; k < 64; k++) {
        float av[4], bv[4];
#pragma unroll
        for (int i = 0; i < 4; i++) av[i] = sh[ty * 4 + i][k];
#pragma unroll
        for (int j = 0; j < 4; j++) bv[j] = sw[tx * 4 + j][k];
#pragma unroll
        for (int i = 0; i < 4; i++)
#pragma unroll
            for (int j = 0; j < 4; j++) acc[i][j] = fmaf(av[i], bv[j], acc[i][j]);
    }

#pragma unroll
    for (int i = 0; i < 4; i++)
#pragma unroll
        for (int j = 0; j < 4; j++) {
            int bb = ty * 4 + i;
            int o  = o0 + tx * 4 + j;
            g_part[(size_t)ks * (BATCH * ODIM) + bb * ODIM + o] = acc[i][j];
        }
}

__global__ void out_reduce_kernel(const float* __restrict__ b_ho, float* __restrict__ Y) {
    int i = blockIdx.x * blockDim.x + threadIdx.x;
    float s = b_ho[i & (ODIM - 1)];
#pragma unroll
    for (int k = 0; k < KSLICES; k++) s += g_part[(size_t)k * (BATCH * ODIM) + i];
    Y[i] = s;
}

// ---------------------------------------------------------------------------
// Launch
// ---------------------------------------------------------------------------
extern "C" void kernel_launch(void* const* d_in, const int* in_sizes, int n_in,
                              void* d_out, int out_size) {
    const float* X    = (const float*)d_in[0];   // [1024,64,512]
    const float* W_ih = (const float*)d_in[1];   // [2048,512]
    const float* hh   = (const float*)d_in[2];   // [2048]
    const float* W_ho = (const float*)d_in[3];   // [512,2048]
    const float* b_ho = (const float*)d_in[4];   // [512]
    float* Y = (float*)d_out;                    // [64,512]

    // 1) fused fp16 conversion prepass (X and W)
    cvt_kernel<<<(NX_H8 + NW_H8) / 256, 256>>>((const float4*)X,
                                               (const float4*)W_ih);

    // 2) big GEMM u = Xh @ Wh^T (fp16 mma, ldmatrix, single barrier/ktile)
    dim3 ggrid(HDIM / BN, MTOT / BM);  // (16, 512) x-major: N-tiles share A in L2
    gemm_u_kernel<<<ggrid, 256>>>();

    // 3) sequential scan
    scan_kernel<<<(BATCH * HDIM / 2) / 64, 64>>>(hh);

    // 4) output GEMM (split-K) + reduce
    dim3 ogrid(ODIM / 64, KSLICES);
    out_partial_kernel<<<ogrid, 256>>>(W_ho);
    out_reduce_kernel<<<(BATCH * ODIM) / 256, 256>>>(b_ho, Y);
}

// round 14
// speedup vs baseline: 1.5752x; 1.5752x over previous
#include <cuda_runtime.h>
#include <cuda_fp16.h>
#include <cstdint>

// Problem dims
#define S_LEN 1024
#define BATCH 64
#define IDIM  512
#define HDIM  2048
#define ODIM  512
#define MTOT  (S_LEN * BATCH)   // 65536

// ---------------------------------------------------------------------------
// Device scratch (no cudaMalloc allowed)
// ---------------------------------------------------------------------------
__device__ __half g_Xh[(size_t)MTOT * IDIM];        // 64 MB   fp16 X
__device__ __half g_Wh[(size_t)HDIM * IDIM];        // 2 MB    fp16 W_ih
__device__ __half g_uh[(size_t)MTOT * HDIM];        // 256 MB  u (fp16)
__device__ float  g_h [(size_t)BATCH * HDIM];       // 512 KB  h_final[b][h]
__device__ float  g_part[(size_t)64 * BATCH * ODIM];// 8 MB    split-K partials

// ---------------------------------------------------------------------------
// Helpers
// ---------------------------------------------------------------------------
__device__ __forceinline__ void cp_async16(uint32_t saddr, const void* gptr) {
    asm volatile("cp.async.cg.shared.global [%0], [%1], 16;\n"
                 :: "r"(saddr), "l"(gptr) : "memory");
}
#define CP_COMMIT() asm volatile("cp.async.commit_group;\n" ::: "memory")
#define CP_WAIT(N)  asm volatile("cp.async.wait_group %0;\n" :: "n"(N) : "memory")

#define LDSM_X4(r0, r1, r2, r3, addr) \
    asm volatile("ldmatrix.sync.aligned.m8n8.x4.shared.b16 {%0,%1,%2,%3}, [%4];" \
                 : "=r"(r0), "=r"(r1), "=r"(r2), "=r"(r3) : "r"(addr))

struct alignas(16) H8 { __half2 a, b, c, d; };

// ---------------------------------------------------------------------------
// Kernel 1: fused fp32 -> fp16 conversion prepass (X then W in one grid)
// ---------------------------------------------------------------------------
#define NX_H8 (MTOT * IDIM / 8)          // 4,194,304
#define NW_H8 (HDIM * IDIM / 8)          // 131,072

__global__ void cvt_kernel(const float4* __restrict__ X,
                           const float4* __restrict__ W) {
    int i = blockIdx.x * blockDim.x + threadIdx.x;
    const float4* src;
    H8* dst;
    int j;
    if (i < NX_H8) {
        src = X;  dst = reinterpret_cast<H8*>(g_Xh);  j = i;
    } else {
        src = W;  dst = reinterpret_cast<H8*>(g_Wh);  j = i - NX_H8;
    }
    float4 v0 = src[2 * j], v1 = src[2 * j + 1];
    H8 o;
    o.a = __floats2half2_rn(v0.x, v0.y);
    o.b = __floats2half2_rn(v0.z, v0.w);
    o.c = __floats2half2_rn(v1.x, v1.y);
    o.d = __floats2half2_rn(v1.z, v1.w);
    dst[j] = o;
}

// ---------------------------------------------------------------------------
// Kernel 2: u = Xh @ Wh^T via mma.sync.m16n8k16 + ldmatrix.
// EXACT R10 configuration — best measured (357 TF/s).  FROZEN: R11 (fat
// warps), R12 (4-stage), R13 (barrier removal) all regressed.
// ---------------------------------------------------------------------------
#define BM 128
#define BN 128
#define BKH 32
#define KTILES (IDIM / BKH)        // 16
#define NSTG 3
#define LDAH 40
#define STAGE_HALFS (BM * LDAH)
#define STAGE_BYTES (STAGE_HALFS * 2)

__global__ __launch_bounds__(256, 2) void gemm_u_kernel() {
    __shared__ __half sA[NSTG][STAGE_HALFS];
    __shared__ __half sB[NSTG][STAGE_HALFS];

    const int tid  = threadIdx.x;
    const int lane = tid & 31;
    const int warp = tid >> 5;
    const int wm   = warp >> 1;   // 0..3
    const int wn   = warp & 1;    // 0..1
    const int g    = lane >> 2;   // 0..7
    const int tg   = lane & 3;    // 0..3

    const int m0 = blockIdx.y * BM;
    const int n0 = blockIdx.x * BN;

    const uint32_t sA_base = (uint32_t)__cvta_generic_to_shared(&sA[0][0]);
    const uint32_t sB_base = (uint32_t)__cvta_generic_to_shared(&sB[0][0]);

    const int ro  = lane & 7;
    const int sel = lane >> 3;
    uint32_t offA[2], offB[4];
#pragma unroll
    for (int mi = 0; mi < 2; mi++) {
        int rowA = wm * 32 + mi * 16 + (sel & 1) * 8 + ro;
        int colA = (sel >> 1) * 8;
        offA[mi] = (uint32_t)(rowA * LDAH + colA) * 2;
    }
#pragma unroll
    for (int p = 0; p < 4; p++) {
        int rowB = wn * 64 + p * 16 + (sel >> 1) * 8 + ro;
        int colB = (sel & 1) * 8;
        offB[p] = (uint32_t)(rowB * LDAH + colB) * 2;
    }

    float c[2][8][4];
#pragma unroll
    for (int mi = 0; mi < 2; mi++)
#pragma unroll
        for (int ni = 0; ni < 8; ni++)
#pragma unroll
            for (int r = 0; r < 4; r++) c[mi][ni][r] = 0.0f;

    auto loadAB = [&](int stage, int kt) {
#pragma unroll
        for (int i = 0; i < 2; i++) {
            int lin = tid + i * 256;
            int row = lin >> 2, c16 = lin & 3;
            cp_async16(sA_base + stage * STAGE_BYTES + (row * LDAH + c16 * 8) * 2,
                       g_Xh + (size_t)(m0 + row) * IDIM + kt * BKH + c16 * 8);
            cp_async16(sB_base + stage * STAGE_BYTES + (row * LDAH + c16 * 8) * 2,
                       g_Wh + (size_t)(n0 + row) * IDIM + kt * BKH + c16 * 8);
        }
    };

    loadAB(0, 0); CP_COMMIT();
    loadAB(1, 1); CP_COMMIT();

    for (int kt = 0; kt < KTILES; ++kt) {
        if (kt < KTILES - 1) { CP_WAIT(1); } else { CP_WAIT(0); }
        __syncthreads();

        if (kt + 2 < KTILES) { loadAB((kt + 2) % NSTG, kt + 2); CP_COMMIT(); }

        const uint32_t aStage = sA_base + (kt % NSTG) * STAGE_BYTES;
        const uint32_t bStage = sB_base + (kt % NSTG) * STAGE_BYTES;
#pragma unroll
        for (int kf = 0; kf < 2; ++kf) {
            const uint32_t kbyte = kf * 32;   // 16 halves
            uint32_t a[2][4], bf[8][2];
#pragma unroll
            for (int mi = 0; mi < 2; mi++)
                LDSM_X4(a[mi][0], a[mi][1], a[mi][2], a[mi][3],
                        aStage + offA[mi] + kbyte);
#pragma unroll
            for (int p = 0; p < 4; p++)
                LDSM_X4(bf[2 * p][0], bf[2 * p][1], bf[2 * p + 1][0],
                        bf[2 * p + 1][1], bStage + offB[p] + kbyte);
#pragma unroll
            for (int mi = 0; mi < 2; mi++)
#pragma unroll
                for (int ni = 0; ni < 8; ni++) {
                    asm volatile(
                        "mma.sync.aligned.m16n8k16.row.col.f32.f16.f16.f32 "
                        "{%0,%1,%2,%3}, {%4,%5,%6,%7}, {%8,%9}, {%0,%1,%2,%3};"
                        : "+f"(c[mi][ni][0]), "+f"(c[mi][ni][1]),
                          "+f"(c[mi][ni][2]), "+f"(c[mi][ni][3])
                        : "r"(a[mi][0]), "r"(a[mi][1]), "r"(a[mi][2]), "r"(a[mi][3]),
                          "r"(bf[ni][0]), "r"(bf[ni][1]));
                }
        }
        __syncthreads();
    }

#pragma unroll
    for (int mi = 0; mi < 2; mi++) {
#pragma unroll
        for (int ni = 0; ni < 8; ni++) {
            int r     = m0 + wm * 32 + mi * 16 + g;
            int cbase = n0 + wn * 64 + ni * 8 + 2 * tg;
            __half2 v0 = __floats2half2_rn(c[mi][ni][0], c[mi][ni][1]);
            __half2 v1 = __floats2half2_rn(c[mi][ni][2], c[mi][ni][3]);
            *reinterpret_cast<__half2*>(g_uh + (size_t)r * HDIM + cbase)       = v0;
            *reinterpret_cast<__half2*>(g_uh + (size_t)(r + 8) * HDIM + cbase) = v1;
        }
    }
}

// ---------------------------------------------------------------------------
// Kernel 3: sequential scan h = |u_t + hh*h|, fp16 u, 4 channels/thread
// via uint2 loads (half the load instructions per byte vs half2 — scan was
// issue-limited at 36.6%).  Depth-32 ring: 32768 thr x 32 x 8B = 8 MB in
// flight.  512 CTAs x 64 thr (DRAM-bound: wave imbalance immaterial).
// ---------------------------------------------------------------------------
#define SCAN_DEPTH 32

__global__ void scan_kernel(const float* __restrict__ hh) {
    const int ch4 = blockIdx.x * blockDim.x + threadIdx.x;   // uint2 index
    const int hbase = (4 * ch4) & (HDIM - 1);
    const float a0 = hh[hbase];
    const float a1 = hh[hbase + 1];
    const float a2 = hh[hbase + 2];
    const float a3 = hh[hbase + 3];
    const uint2* p = reinterpret_cast<const uint2*>(g_uh) + ch4;
    const size_t stride = (size_t)BATCH * HDIM / 4;          // 32768 uint2s

    uint2 buf[SCAN_DEPTH];
#pragma unroll
    for (int i = 0; i < SCAN_DEPTH; i++) buf[i] = p[(size_t)i * stride];

    float h0 = 0.0f, h1 = 0.0f, h2 = 0.0f, h3 = 0.0f;
    for (int s0 = 0; s0 < S_LEN; s0 += SCAN_DEPTH) {
#pragma unroll
        for (int i = 0; i < SCAN_DEPTH; i++) {
            uint2 v = buf[i];
            int ns = s0 + SCAN_DEPTH + i;
            if (ns < S_LEN) buf[i] = p[(size_t)ns * stride];
            float2 u01 = __half22float2(*reinterpret_cast<__half2*>(&v.x));
            float2 u23 = __half22float2(*reinterpret_cast<__half2*>(&v.y));
            h0 = fabsf(fmaf(a0, h0, u01.x));
            h1 = fabsf(fmaf(a1, h1, u01.y));
            h2 = fabsf(fmaf(a2, h2, u23.x));
            h3 = fabsf(fmaf(a3, h3, u23.y));
        }
    }
    float4 out = make_float4(h0, h1, h2, h3);
    *reinterpret_cast<float4*>(g_h + 4 * ch4) = out;
}

// ---------------------------------------------------------------------------
// Kernel 4/5: split-K output GEMM (KSLICES=64 for parallelism) + reduce
// ---------------------------------------------------------------------------
#define KSLICES 64

__global__ __launch_bounds__(256) void out_partial_kernel(const float* __restrict__ W_ho) {
    __shared__ float sh[64][33];
    __shared__ float sw[64][33];
    const int tid = threadIdx.x;
    const int tx = tid & 15, ty = tid >> 4;
    const int o0 = blockIdx.x * 64;
    const int ks = blockIdx.y;
    const int kbase = ks * 32;

    float acc[4][4];
#pragma unroll
    for (int i = 0; i < 4; i++)
#pragma unroll
        for (int j = 0; j < 4; j++) acc[i][j] = 0.0f;

#pragma unroll
    for (int i = 0; i < 8; i++) {
        int lin = tid + i * 256;
        int row = lin >> 5, col = lin & 31;
        sh[row][col] = g_h[(size_t)row * HDIM + kbase + col];
        sw[row][col] = W_ho[(size_t)(o0 + row) * HDIM + kbase + col];
    }
    __syncthreads();
#pragma unroll 8
    for (int k = 0; k < 32; k++) {
        float av[4], bv[4];
#pragma unroll
        for (int i = 0; i < 4; i++) av[i] = sh[ty * 4 + i][k];
#pragma unroll
        for (int j = 0; j < 4; j++) bv[j] = sw[tx * 4 + j][k];
#pragma unroll
        for (int i = 0; i < 4; i++)
#pragma unroll
            for (int j = 0; j < 4; j++) acc[i][j] = fmaf(av[i], bv[j], acc[i][j]);
    }

#pragma unroll
    for (int i = 0; i < 4; i++)
#pragma unroll
        for (int j = 0; j < 4; j++) {
            int bb = ty * 4 + i;
            int o  = o0 + tx * 4 + j;
            g_part[(size_t)ks * (BATCH * ODIM) + bb * ODIM + o] = acc[i][j];
        }
}

__global__ void out_reduce_kernel(const float* __restrict__ b_ho, float* __restrict__ Y) {
    int i = blockIdx.x * blockDim.x + threadIdx.x;
    float s = b_ho[i & (ODIM - 1)];
#pragma unroll
    for (int k = 0; k < KSLICES; k++) s += g_part[(size_t)k * (BATCH * ODIM) + i];
    Y[i] = s;
}

// ---------------------------------------------------------------------------
// Launch
// ---------------------------------------------------------------------------
extern "C" void kernel_launch(void* const* d_in, const int* in_sizes, int n_in,
                              void* d_out, int out_size) {
    const float* X    = (const float*)d_in[0];   // [1024,64,512]
    const float* W_ih = (const float*)d_in[1];   // [2048,512]
    const float* hh   = (const float*)d_in[2];   // [2048]
    const float* W_ho = (const float*)d_in[3];   // [512,2048]
    const float* b_ho = (const float*)d_in[4];   // [512]
    float* Y = (float*)d_out;                    // [64,512]

    // 1) fused fp16 conversion prepass (X and W)
    cvt_kernel<<<(NX_H8 + NW_H8) / 256, 256>>>((const float4*)X,
                                               (const float4*)W_ih);

    // 2) big GEMM u = Xh @ Wh^T (EXACT R10 — frozen)
    dim3 ggrid(HDIM / BN, MTOT / BM);  // (16, 512)
    gemm_u_kernel<<<ggrid, 256>>>();

    // 3) sequential scan (4 ch/thread, uint2 loads, depth-32 ring)
    scan_kernel<<<(BATCH * HDIM / 4) / 64, 64>>>(hh);

    // 4) output GEMM (split-K=64) + reduce
    dim3 ogrid(ODIM / 64, KSLICES);
    out_partial_kernel<<<ogrid, 256>>>(W_ho);
    out_reduce_kernel<<<(BATCH * ODIM) / 256, 256>>>(b_ho, Y);
}

// round 15
// speedup vs baseline: 1.6472x; 1.0457x over previous
#include <cuda_runtime.h>
#include <cuda_fp16.h>
#include <cstdint>

// Problem dims
#define S_LEN 1024
#define BATCH 64
#define IDIM  512
#define HDIM  2048
#define ODIM  512
#define MTOT  (S_LEN * BATCH)   // 65536

// ---------------------------------------------------------------------------
// Device scratch (no cudaMalloc allowed)
// ---------------------------------------------------------------------------
__device__ __half g_Xh[(size_t)MTOT * IDIM];        // 64 MB   fp16 X
__device__ __half g_Wh[(size_t)HDIM * IDIM];        // 2 MB    fp16 W_ih
__device__ __half g_uh[(size_t)MTOT * HDIM];        // 256 MB  u (fp16)
__device__ float  g_h [(size_t)BATCH * HDIM];       // 512 KB  h_final[b][h]
__device__ float  g_part[(size_t)64 * BATCH * ODIM];// 8 MB    split-K partials

// ---------------------------------------------------------------------------
// Helpers
// ---------------------------------------------------------------------------
__device__ __forceinline__ void cp_async16(uint32_t saddr, const void* gptr) {
    asm volatile("cp.async.cg.shared.global [%0], [%1], 16;\n"
                 :: "r"(saddr), "l"(gptr) : "memory");
}
#define CP_COMMIT() asm volatile("cp.async.commit_group;\n" ::: "memory")
#define CP_WAIT(N)  asm volatile("cp.async.wait_group %0;\n" :: "n"(N) : "memory")

#define LDSM_X4(r0, r1, r2, r3, addr) \
    asm volatile("ldmatrix.sync.aligned.m8n8.x4.shared.b16 {%0,%1,%2,%3}, [%4];" \
                 : "=r"(r0), "=r"(r1), "=r"(r2), "=r"(r3) : "r"(addr))

struct alignas(16) H8 { __half2 a, b, c, d; };

// ---------------------------------------------------------------------------
// Kernel 1: fused fp32 -> fp16 conversion prepass (X then W in one grid)
// ---------------------------------------------------------------------------
#define NX_H8 (MTOT * IDIM / 8)          // 4,194,304
#define NW_H8 (HDIM * IDIM / 8)          // 131,072

__global__ void cvt_kernel(const float4* __restrict__ X,
                           const float4* __restrict__ W) {
    int i = blockIdx.x * blockDim.x + threadIdx.x;
    const float4* src;
    H8* dst;
    int j;
    if (i < NX_H8) {
        src = X;  dst = reinterpret_cast<H8*>(g_Xh);  j = i;
    } else {
        src = W;  dst = reinterpret_cast<H8*>(g_Wh);  j = i - NX_H8;
    }
    float4 v0 = src[2 * j], v1 = src[2 * j + 1];
    H8 o;
    o.a = __floats2half2_rn(v0.x, v0.y);
    o.b = __floats2half2_rn(v0.z, v0.w);
    o.c = __floats2half2_rn(v1.x, v1.y);
    o.d = __floats2half2_rn(v1.z, v1.w);
    dst[j] = o;
}

// ---------------------------------------------------------------------------
// Kernel 2: u = Xh @ Wh^T via mma.sync.m16n8k16 + ldmatrix.
// R10 pipeline topology unchanged (3 stages, depth-2 prefetch, BOTH
// barriers per ktile, 8 warps x 32x64) — single variable vs R14: BKH
// 32 -> 64.  8 ktiles instead of 16 => half the CP_WAIT/barrier events,
// 4 uninterrupted kf-steps between syncs.  LDAH=72 keeps ldmatrix
// conflict-free (row starts at banks {0,4,..,28}; 16B spans tile all 32).
// 108 KB dynamic smem/CTA, 2 CTAs/SM.
// ---------------------------------------------------------------------------
#define BM 128
#define BN 128
#define BKH 64                      // halves per k-tile (128 B/row)
#define KTILES (IDIM / BKH)         // 8
#define NSTG 3
#define LDAH 72                     // padded row length in halves (144 B)
#define STAGE_HALFS (BM * LDAH)     // 9216
#define STAGE_BYTES (STAGE_HALFS * 2)               // 18432
#define GEMM_SMEM (2 * NSTG * STAGE_BYTES)          // 110592

__global__ __launch_bounds__(256, 2) void gemm_u_kernel() {
    extern __shared__ __half smem[];
    __half* sA = smem;
    __half* sB = smem + NSTG * STAGE_HALFS;

    const int tid  = threadIdx.x;
    const int lane = tid & 31;
    const int warp = tid >> 5;
    const int wm   = warp >> 1;   // 0..3
    const int wn   = warp & 1;    // 0..1
    const int g    = lane >> 2;   // 0..7
    const int tg   = lane & 3;    // 0..3

    const int m0 = blockIdx.y * BM;
    const int n0 = blockIdx.x * BN;

    const uint32_t sA_base = (uint32_t)__cvta_generic_to_shared(sA);
    const uint32_t sB_base = (uint32_t)__cvta_generic_to_shared(sB);

    // Per-lane ldmatrix byte offsets (R10 mapping, LDAH=72).
    const int ro  = lane & 7;
    const int sel = lane >> 3;
    uint32_t offA[2], offB[4];
#pragma unroll
    for (int mi = 0; mi < 2; mi++) {
        int rowA = wm * 32 + mi * 16 + (sel & 1) * 8 + ro;
        int colA = (sel >> 1) * 8;
        offA[mi] = (uint32_t)(rowA * LDAH + colA) * 2;
    }
#pragma unroll
    for (int p = 0; p < 4; p++) {
        int rowB = wn * 64 + p * 16 + (sel >> 1) * 8 + ro;
        int colB = (sel & 1) * 8;
        offB[p] = (uint32_t)(rowB * LDAH + colB) * 2;
    }

    float c[2][8][4];
#pragma unroll
    for (int mi = 0; mi < 2; mi++)
#pragma unroll
        for (int ni = 0; ni < 8; ni++)
#pragma unroll
            for (int r = 0; r < 4; r++) c[mi][ni][r] = 0.0f;

    // Loader: 128 rows x 64 halves = 8 chunks(16B)/row = 1024 chunks per
    // operand; 256 threads -> 4 chunks each per operand.
    auto loadAB = [&](int stage, int kt) {
#pragma unroll
        for (int i = 0; i < 4; i++) {
            int lin = tid + i * 256;
            int row = lin >> 3, c16 = lin & 7;
            cp_async16(sA_base + stage * STAGE_BYTES + (row * LDAH + c16 * 8) * 2,
                       g_Xh + (size_t)(m0 + row) * IDIM + kt * BKH + c16 * 8);
            cp_async16(sB_base + stage * STAGE_BYTES + (row * LDAH + c16 * 8) * 2,
                       g_Wh + (size_t)(n0 + row) * IDIM + kt * BKH + c16 * 8);
        }
    };

    loadAB(0, 0); CP_COMMIT();
    loadAB(1, 1); CP_COMMIT();

    for (int kt = 0; kt < KTILES; ++kt) {
        if (kt < KTILES - 1) { CP_WAIT(1); } else { CP_WAIT(0); }
        __syncthreads();

        if (kt + 2 < KTILES) { loadAB((kt + 2) % NSTG, kt + 2); CP_COMMIT(); }

        const uint32_t aStage = sA_base + (kt % NSTG) * STAGE_BYTES;
        const uint32_t bStage = sB_base + (kt % NSTG) * STAGE_BYTES;
#pragma unroll
        for (int kf = 0; kf < 4; ++kf) {
            const uint32_t kbyte = kf * 32;   // 16 halves
            uint32_t a[2][4], bf[8][2];
#pragma unroll
            for (int mi = 0; mi < 2; mi++)
                LDSM_X4(a[mi][0], a[mi][1], a[mi][2], a[mi][3],
                        aStage + offA[mi] + kbyte);
#pragma unroll
            for (int p = 0; p < 4; p++)
                LDSM_X4(bf[2 * p][0], bf[2 * p][1], bf[2 * p + 1][0],
                        bf[2 * p + 1][1], bStage + offB[p] + kbyte);
#pragma unroll
            for (int mi = 0; mi < 2; mi++)
#pragma unroll
                for (int ni = 0; ni < 8; ni++) {
                    asm volatile(
                        "mma.sync.aligned.m16n8k16.row.col.f32.f16.f16.f32 "
                        "{%0,%1,%2,%3}, {%4,%5,%6,%7}, {%8,%9}, {%0,%1,%2,%3};"
                        : "+f"(c[mi][ni][0]), "+f"(c[mi][ni][1]),
                          "+f"(c[mi][ni][2]), "+f"(c[mi][ni][3])
                        : "r"(a[mi][0]), "r"(a[mi][1]), "r"(a[mi][2]), "r"(a[mi][3]),
                          "r"(bf[ni][0]), "r"(bf[ni][1]));
                }
        }
        __syncthreads();
    }

#pragma unroll
    for (int mi = 0; mi < 2; mi++) {
#pragma unroll
        for (int ni = 0; ni < 8; ni++) {
            int r     = m0 + wm * 32 + mi * 16 + g;
            int cbase = n0 + wn * 64 + ni * 8 + 2 * tg;
            __half2 v0 = __floats2half2_rn(c[mi][ni][0], c[mi][ni][1]);
            __half2 v1 = __floats2half2_rn(c[mi][ni][2], c[mi][ni][3]);
            *reinterpret_cast<__half2*>(g_uh + (size_t)r * HDIM + cbase)       = v0;
            *reinterpret_cast<__half2*>(g_uh + (size_t)(r + 8) * HDIM + cbase) = v1;
        }
    }
}

// ---------------------------------------------------------------------------
// Kernel 3: sequential scan h = |u_t + hh*h|, fp16 u, 4 channels/thread
// via uint2 loads.  Depth-32 ring (8 MB in flight).  512 CTAs x 64 thr.
// ---------------------------------------------------------------------------
#define SCAN_DEPTH 32

__global__ void scan_kernel(const float* __restrict__ hh) {
    const int ch4 = blockIdx.x * blockDim.x + threadIdx.x;   // uint2 index
    const int hbase = (4 * ch4) & (HDIM - 1);
    const float a0 = hh[hbase];
    const float a1 = hh[hbase + 1];
    const float a2 = hh[hbase + 2];
    const float a3 = hh[hbase + 3];
    const uint2* p = reinterpret_cast<const uint2*>(g_uh) + ch4;
    const size_t stride = (size_t)BATCH * HDIM / 4;          // 32768 uint2s

    uint2 buf[SCAN_DEPTH];
#pragma unroll
    for (int i = 0; i < SCAN_DEPTH; i++) buf[i] = p[(size_t)i * stride];

    float h0 = 0.0f, h1 = 0.0f, h2 = 0.0f, h3 = 0.0f;
    for (int s0 = 0; s0 < S_LEN; s0 += SCAN_DEPTH) {
#pragma unroll
        for (int i = 0; i < SCAN_DEPTH; i++) {
            uint2 v = buf[i];
            int ns = s0 + SCAN_DEPTH + i;
            if (ns < S_LEN) buf[i] = p[(size_t)ns * stride];
            float2 u01 = __half22float2(*reinterpret_cast<__half2*>(&v.x));
            float2 u23 = __half22float2(*reinterpret_cast<__half2*>(&v.y));
            h0 = fabsf(fmaf(a0, h0, u01.x));
            h1 = fabsf(fmaf(a1, h1, u01.y));
            h2 = fabsf(fmaf(a2, h2, u23.x));
            h3 = fabsf(fmaf(a3, h3, u23.y));
        }
    }
    float4 out = make_float4(h0, h1, h2, h3);
    *reinterpret_cast<float4*>(g_h + 4 * ch4) = out;
}

// ---------------------------------------------------------------------------
// Kernel 4/5: split-K output GEMM (KSLICES=64) + reduce
// ---------------------------------------------------------------------------
#define KSLICES 64

__global__ __launch_bounds__(256) void out_partial_kernel(const float* __restrict__ W_ho) {
    __shared__ float sh[64][33];
    __shared__ float sw[64][33];
    const int tid = threadIdx.x;
    const int tx = tid & 15, ty = tid >> 4;
    const int o0 = blockIdx.x * 64;
    const int ks = blockIdx.y;
    const int kbase = ks * 32;

    float acc[4][4];
#pragma unroll
    for (int i = 0; i < 4; i++)
#pragma unroll
        for (int j = 0; j < 4; j++) acc[i][j] = 0.0f;

#pragma unroll
    for (int i = 0; i < 8; i++) {
        int lin = tid + i * 256;
        int row = lin >> 5, col = lin & 31;
        sh[row][col] = g_h[(size_t)row * HDIM + kbase + col];
        sw[row][col] = W_ho[(size_t)(o0 + row) * HDIM + kbase + col];
    }
    __syncthreads();
#pragma unroll 8
    for (int k = 0; k < 32; k++) {
        float av[4], bv[4];
#pragma unroll
        for (int i = 0; i < 4; i++) av[i] = sh[ty * 4 + i][k];
#pragma unroll
        for (int j = 0; j < 4; j++) bv[j] = sw[tx * 4 + j][k];
#pragma unroll
        for (int i = 0; i < 4; i++)
#pragma unroll
            for (int j = 0; j < 4; j++) acc[i][j] = fmaf(av[i], bv[j], acc[i][j]);
    }

#pragma unroll
    for (int i = 0; i < 4; i++)
#pragma unroll
        for (int j = 0; j < 4; j++) {
            int bb = ty * 4 + i;
            int o  = o0 + tx * 4 + j;
            g_part[(size_t)ks * (BATCH * ODIM) + bb * ODIM + o] = acc[i][j];
        }
}

__global__ void out_reduce_kernel(const float* __restrict__ b_ho, float* __restrict__ Y) {
    int i = blockIdx.x * blockDim.x + threadIdx.x;
    float s = b_ho[i & (ODIM - 1)];
#pragma unroll
    for (int k = 0; k < KSLICES; k++) s += g_part[(size_t)k * (BATCH * ODIM) + i];
    Y[i] = s;
}

// ---------------------------------------------------------------------------
// Launch
// ---------------------------------------------------------------------------
extern "C" void kernel_launch(void* const* d_in, const int* in_sizes, int n_in,
                              void* d_out, int out_size) {
    const float* X    = (const float*)d_in[0];   // [1024,64,512]
    const float* W_ih = (const float*)d_in[1];   // [2048,512]
    const float* hh   = (const float*)d_in[2];   // [2048]
    const float* W_ho = (const float*)d_in[3];   // [512,2048]
    const float* b_ho = (const float*)d_in[4];   // [512]
    float* Y = (float*)d_out;                    // [64,512]

    // 1) fused fp16 conversion prepass (X and W)
    cvt_kernel<<<(NX_H8 + NW_H8) / 256, 256>>>((const float4*)X,
                                               (const float4*)W_ih);

    // 2) big GEMM u = Xh @ Wh^T (R10 topology, BKH=64, dynamic smem)
    cudaFuncSetAttribute(gemm_u_kernel,
                         cudaFuncAttributeMaxDynamicSharedMemorySize, GEMM_SMEM);
    dim3 ggrid(HDIM / BN, MTOT / BM);  // (16, 512)
    gemm_u_kernel<<<ggrid, 256, GEMM_SMEM>>>();

    // 3) sequential scan (4 ch/thread, uint2 loads, depth-32 ring)
    scan_kernel<<<(BATCH * HDIM / 4) / 64, 64>>>(hh);

    // 4) output GEMM (split-K=64) + reduce
    dim3 ogrid(ODIM / 64, KSLICES);
    out_partial_kernel<<<ogrid, 256>>>(W_ho);
    out_reduce_kernel<<<(BATCH * ODIM) / 256, 256>>>(b_ho, Y);
}